// round 10
// baseline (speedup 1.0000x reference)
#include <cuda_runtime.h>
#include <cuda_fp16.h>
#include <math.h>
#include <stdint.h>

#define Bb 8
#define Tt 1024
#define Cc 1024
#define NHEAD 16
#define HDIM 64
#define BHt (Bb*NHEAD)     // 128
#define Mm (Bb*Tt)         // 8192
#define N1 (3*Cc)          // 3072
#define KT2 16             // 1024/64 k-tiles (BK=64)

// ------------------------- device scratch (no allocs allowed) --------------
__device__ __half g_xhi[(size_t)Mm*Cc],  g_xlo[(size_t)Mm*Cc];
__device__ __half g_w1h[(size_t)N1*Cc];                    // weights single fp16
__device__ __half g_w2h[(size_t)Cc*Cc];
__device__ __half g_yhi[(size_t)Mm*Cc],  g_ylo[(size_t)Mm*Cc];
__device__ __half g_Qhi[(size_t)BHt*Tt*HDIM], g_Qlo[(size_t)BHt*Tt*HDIM]; // post-rope, x0.125
__device__ __half g_Kh [(size_t)BHt*Tt*HDIM];              // post-rope, single fp16
__device__ __half g_Vth[(size_t)BHt*HDIM*Tt];              // [bh][d][t], single fp16

// ------------------------------ PTX helpers --------------------------------
__device__ __forceinline__ uint32_t smem_u32(const void* p) {
    uint32_t a;
    asm("{ .reg .u64 t; cvta.to.shared.u64 t, %1; cvt.u32.u64 %0, t; }"
        : "=r"(a) : "l"(p));
    return a;
}

#define CP16(dst, src) \
    asm volatile("cp.async.cg.shared.global [%0], [%1], 16;" \
                 :: "r"(dst), "l"(src) : "memory")
#define CP_COMMIT() asm volatile("cp.async.commit_group;" ::: "memory")
#define CP_WAIT1()  asm volatile("cp.async.wait_group 1;" ::: "memory")
#define CP_WAIT0()  asm volatile("cp.async.wait_group 0;" ::: "memory")

#define LDSM4(r0, r1, r2, r3, a) \
    asm volatile("ldmatrix.sync.aligned.m8n8.x4.shared.b16 {%0,%1,%2,%3}, [%4];" \
                 : "=r"(r0), "=r"(r1), "=r"(r2), "=r"(r3) : "r"(a))

__device__ __forceinline__ void mma16816(float c[4], const uint32_t a[4],
                                         uint32_t b0, uint32_t b1) {
    asm volatile("mma.sync.aligned.m16n8k16.row.col.f32.f16.f16.f32 "
                 "{%0,%1,%2,%3}, {%4,%5,%6,%7}, {%8,%9}, {%0,%1,%2,%3};"
                 : "+f"(c[0]), "+f"(c[1]), "+f"(c[2]), "+f"(c[3])
                 : "r"(a[0]), "r"(a[1]), "r"(a[2]), "r"(a[3]),
                   "r"(b0), "r"(b1));
}

// two floats -> packed fp16x2 hi + residual lo
__device__ __forceinline__ void split2h(float x, float y, uint32_t& hi, uint32_t& lo) {
    __half2 h = __floats2half2_rn(x, y);
    float2 hf = __half22float2(h);
    __half2 l = __floats2half2_rn(x - hf.x, y - hf.y);
    hi = *reinterpret_cast<uint32_t*>(&h);
    lo = *reinterpret_cast<uint32_t*>(&l);
}
__device__ __forceinline__ uint32_t pack2h(float x, float y) {
    __half2 h = __floats2half2_rn(x, y);
    return *reinterpret_cast<uint32_t*>(&h);
}

// ---------------------------------------------------------------------------
// fp32 -> fp16 conversions.  W=0: x -> hi/lo.  W=1: w1 -> single.  W=2: w2.
// ---------------------------------------------------------------------------
template<int W>
__global__ __launch_bounds__(256)
void cvt_kernel(const float* __restrict__ src, int n4)
{
    int i = blockIdx.x * blockDim.x + threadIdx.x;
    if (i >= n4) return;
    float4 v = ((const float4*)src)[i];
    if (W == 0) {
        uint32_t h01, l01, h23, l23;
        split2h(v.x, v.y, h01, l01);
        split2h(v.z, v.w, h23, l23);
        ((uint2*)g_xhi)[i] = make_uint2(h01, h23);
        ((uint2*)g_xlo)[i] = make_uint2(l01, l23);
    } else {
        uint2 o = make_uint2(pack2h(v.x, v.y), pack2h(v.z, v.w));
        if (W == 1) ((uint2*)g_w1h)[i] = o;
        else        ((uint2*)g_w2h)[i] = o;
    }
}

// ---------------------------------------------------------------------------
// fp16x2 NT GEMM via mma.sync: 128x128 block, 256 thr, 8 warps (2x4, 64x32).
// BK=64 (4 kk-passes per stage -> half the barriers per MMA vs BK=32).
// Smem tiles 128 x 64 fp16, pitch 144B (conflict-free ldmatrix).
// MODE 0: qkv = x @ w1^T + b, fused RoPE epilogue.  MODE 1: y @ w2^T + b.
// ---------------------------------------------------------------------------
#define GPITCH 144
#define T_AHI 0
#define T_ALO 18432
#define T_BH  36864
#define STAGE_BYTES 55296
#define GEMM_SMEM (2*STAGE_BYTES)

#define ROPE_LN_OVER_32 0.2878231366242557f   // ln(10000)/32

__device__ __forceinline__ void gemm_prefetch(uint32_t sdst,
    const __half* a_hi, const __half* a_lo, const __half* b_h)
{
    #pragma unroll
    for (int p = 0; p < 4; p++) {
        CP16(sdst + T_AHI + p * 16, a_hi + p * 8);
        CP16(sdst + T_ALO + p * 16, a_lo + p * 8);
        CP16(sdst + T_BH  + p * 16, b_h  + p * 8);
    }
}

// Epilogue scatter with fused RoPE. v = (col d, col d+1), d even.
__device__ __forceinline__ void scatter_qkv(int m, int n, float2 v)
{
    const int which = n >> 10, c = n & 1023;
    const int h = c >> 6, d = c & 63;
    const int b = m >> 10, t = m & 1023, bh = b * NHEAD + h;
    if (which == 2) {
        size_t i0 = ((size_t)bh * HDIM + d) * Tt + t;
        g_Vth[i0]      = __float2half(v.x);
        g_Vth[i0 + Tt] = __float2half(v.y);
        return;
    }
    const float inv = expf(-(float)(d >> 1) * ROPE_LN_OVER_32);
    float sv, cv;
    sincosf((float)t * inv, &sv, &cv);
    float r1 = v.x * cv - v.y * sv;
    float r2 = v.y * cv + v.x * sv;
    const size_t base = ((size_t)bh * Tt + t) * HDIM + d;
    if (which == 0) {
        uint32_t hi, lo;
        split2h(r1 * 0.125f, r2 * 0.125f, hi, lo);   // Q pre-scaled 1/sqrt(hd)
        *(uint32_t*)&g_Qhi[base] = hi;
        *(uint32_t*)&g_Qlo[base] = lo;
    } else {
        *(uint32_t*)&g_Kh[base] = pack2h(r1, r2);
    }
}

template<int MODE>
__global__ __launch_bounds__(256)
void gemm_fp16x2(const float* __restrict__ bias, float* __restrict__ Cout)
{
    extern __shared__ char smem[];
    const uint32_t sb = smem_u32(smem);
    const int tid  = threadIdx.x;
    const int lane = tid & 31, wid = tid >> 5;
    const int wm = wid >> 2, wn = wid & 3;         // 2 x 4 warp grid, 64x32 tiles
    const int m0 = blockIdx.y * 128, n0 = blockIdx.x * 128;

    const __half* Ahi = (MODE == 0) ? g_xhi : g_yhi;
    const __half* Alo = (MODE == 0) ? g_xlo : g_ylo;
    const __half* Bh  = (MODE == 0) ? g_w1h : g_w2h;

    // cp.async: 2 threads per 128-row; each covers a 64B (32-elem) half
    const int lr = tid >> 1;
    const int lh = tid & 1;
    const size_t gA = (size_t)(m0 + lr) * Cc + lh * 32;
    const size_t gB = (size_t)(n0 + lr) * Cc + lh * 32;
    const uint32_t sOff = (uint32_t)lr * GPITCH + lh * 64;

    const int jq = lane >> 3, rr = lane & 7;
    const int aRow  = wm * 64 + (jq & 1) * 8 + rr;
    const int aColB = (jq >> 1) * 16;
    const int bRow  = wn * 32 + (jq >> 1) * 8 + rr;
    const int bColB = (jq & 1) * 16;

    float acc[4][4][4];
    #pragma unroll
    for (int i = 0; i < 4; i++)
        #pragma unroll
        for (int j = 0; j < 4; j++)
            #pragma unroll
            for (int e = 0; e < 4; e++) acc[i][j][e] = 0.0f;

    gemm_prefetch(sb + sOff, Ahi + gA, Alo + gA, Bh + gB);
    CP_COMMIT();

    for (int kt = 0; kt < KT2; kt++) {
        const int cur = kt & 1;
        if (kt + 1 < KT2) {
            const size_t ko = (size_t)(kt + 1) * 64;
            gemm_prefetch(sb + ((kt + 1) & 1) * STAGE_BYTES + sOff,
                          Ahi + gA + ko, Alo + gA + ko, Bh + gB + ko);
            CP_COMMIT();
            CP_WAIT1();
        } else {
            CP_WAIT0();
        }
        __syncthreads();

        const uint32_t base = sb + cur * STAGE_BYTES;
        #pragma unroll
        for (int kk = 0; kk < 4; kk++) {
            const uint32_t kB = kk * 32;
            uint32_t ah[4][4], al[4][4], bh[2][4];
            #pragma unroll
            for (int mf = 0; mf < 4; mf++) {
                uint32_t addr = base + (uint32_t)(aRow + mf * 16) * GPITCH + aColB + kB;
                LDSM4(ah[mf][0], ah[mf][1], ah[mf][2], ah[mf][3], addr + T_AHI);
                LDSM4(al[mf][0], al[mf][1], al[mf][2], al[mf][3], addr + T_ALO);
            }
            #pragma unroll
            for (int pf = 0; pf < 2; pf++) {
                uint32_t addr = base + (uint32_t)(bRow + pf * 16) * GPITCH + bColB + kB;
                LDSM4(bh[pf][0], bh[pf][1], bh[pf][2], bh[pf][3], addr + T_BH);
            }
            #pragma unroll
            for (int mf = 0; mf < 4; mf++) {
                #pragma unroll
                for (int nt = 0; nt < 4; nt++) {
                    const int pf = nt >> 1, ix = (nt & 1) * 2;
                    mma16816(acc[mf][nt], ah[mf], bh[pf][ix], bh[pf][ix + 1]);
                    mma16816(acc[mf][nt], al[mf], bh[pf][ix], bh[pf][ix + 1]);
                }
            }
        }
        __syncthreads();
    }

    const int gid = lane >> 2, tg = lane & 3;
    #pragma unroll
    for (int mf = 0; mf < 4; mf++) {
        #pragma unroll
        for (int nt = 0; nt < 4; nt++) {
            const int n = n0 + wn * 32 + nt * 8 + tg * 2;
            const float2 bv = *(const float2*)&bias[n];
            const int mA = m0 + wm * 64 + mf * 16 + gid;
            float2 v01 = make_float2(acc[mf][nt][0] + bv.x, acc[mf][nt][1] + bv.y);
            float2 v23 = make_float2(acc[mf][nt][2] + bv.x, acc[mf][nt][3] + bv.y);
            if (MODE == 0) {
                scatter_qkv(mA,     n, v01);
                scatter_qkv(mA + 8, n, v23);
            } else {
                *(float2*)&Cout[(size_t)mA * Cc + n]       = v01;
                *(float2*)&Cout[(size_t)(mA + 8) * Cc + n] = v23;
            }
        }
    }
}

// ---------------------------------------------------------------------------
// Tensor-core flash attention (fp16x2), causal. Block = (qt, bh), 256 thr.
// Q-tile = 128 rows (8 warps x 16 rows) -> each K/V tile load serves 2x rows.
// Smem: Qhi/Qlo 128x72, Kh/Vh 64x72 fp16 (pitch 144B).
// ---------------------------------------------------------------------------
#define FPITCH 144
#define SQH 0
#define SQL 18432
#define SKH 36864
#define SVH 46080
#define FL_SMEM 55296

__global__ __launch_bounds__(256)
void flash_attn_kernel()
{
    extern __shared__ char smem[];
    const uint32_t sb = smem_u32(smem);
    const int tid  = threadIdx.x;
    const int lane = tid & 31, w = tid >> 5;   // warp 0..7
    const int qt = blockIdx.x;     // 0..7  (128-row q-tiles)
    const int bh = blockIdx.y;     // 0..127

    const __half* Qh = g_Qhi + ((size_t)bh * Tt + qt * 128) * HDIM;
    const __half* Ql = g_Qlo + ((size_t)bh * Tt + qt * 128) * HDIM;
    const __half* Kh = g_Kh  + (size_t)bh * Tt * HDIM;
    const __half* Vh = g_Vth + (size_t)bh * HDIM * Tt;

    // load Q tile: 128 rows x 64 cols = 1024 x 8-elem pieces
    #pragma unroll
    for (int ii = 0; ii < 4; ii++) {
        int idx = tid + 256 * ii;
        int r = idx >> 3, c8 = (idx & 7) * 8;
        uint32_t so = (uint32_t)r * FPITCH + c8 * 2;
        *(uint4*)(smem + SQH + so) = *(const uint4*)&Qh[r * 64 + c8];
        *(uint4*)(smem + SQL + so) = *(const uint4*)&Ql[r * 64 + c8];
    }

    const int jq = lane >> 3, rr = lane & 7;
    const uint32_t aAddr = sb + (uint32_t)(w * 16 + (lane & 15)) * FPITCH
                         + (lane >> 4) * 16;
    const uint32_t bBase = (uint32_t)((jq >> 1) * 8 + rr) * FPITCH
                         + (jq & 1) * 16;

    const int gid = lane >> 2, tg = lane & 3;
    const int rowA = w * 16 + gid;         // within 128-row q-tile
    const int rowB = rowA + 8;

    float o[8][4];
    #pragma unroll
    for (int nt = 0; nt < 8; nt++)
        #pragma unroll
        for (int e = 0; e < 4; e++) o[nt][e] = 0.0f;
    float mA = -1e30f, mB = -1e30f, lA = 0.0f, lB = 0.0f;

    const int ktEnd = 2 * qt + 1;          // last k-tile index
    for (int kt = 0; kt <= ktEnd; kt++) {
        __syncthreads();
        // load K (64x64) and V^T (64x64) tiles: 512 x 8-elem pieces
        #pragma unroll
        for (int ii = 0; ii < 2; ii++) {
            int idx = tid + 256 * ii;
            int r = idx >> 3, c8 = (idx & 7) * 8;
            uint32_t so = (uint32_t)r * FPITCH + c8 * 2;
            *(uint4*)(smem + SKH + so) = *(const uint4*)&Kh[(kt * 64 + r) * 64 + c8];
            *(uint4*)(smem + SVH + so) = *(const uint4*)&Vh[(size_t)r * Tt + kt * 64 + c8];
        }
        __syncthreads();

        float c[8][4];
        #pragma unroll
        for (int nt = 0; nt < 8; nt++)
            #pragma unroll
            for (int e = 0; e < 4; e++) c[nt][e] = 0.0f;

        #pragma unroll
        for (int kk = 0; kk < 4; kk++) {
            uint32_t aH[4], aL[4];
            LDSM4(aH[0], aH[1], aH[2], aH[3], aAddr + SQH + kk * 32);
            LDSM4(aL[0], aL[1], aL[2], aL[3], aAddr + SQL + kk * 32);
            #pragma unroll
            for (int pf = 0; pf < 4; pf++) {
                uint32_t bH[4];
                uint32_t ba = sb + bBase + (uint32_t)pf * 16 * FPITCH + kk * 32;
                LDSM4(bH[0], bH[1], bH[2], bH[3], ba + SKH);
                const int nt0 = pf * 2;
                mma16816(c[nt0],     aH, bH[0], bH[1]);
                mma16816(c[nt0],     aL, bH[0], bH[1]);
                mma16816(c[nt0 + 1], aH, bH[2], bH[3]);
                mma16816(c[nt0 + 1], aL, bH[2], bH[3]);
            }
        }

        // causal mask (only tiles that can intersect the diagonal)
        if (kt >= 2 * qt) {
            const int rAg = qt * 128 + rowA;
            const int rBg = rAg + 8;
            #pragma unroll
            for (int nt = 0; nt < 8; nt++) {
                const int colg = kt * 64 + nt * 8 + tg * 2;
                if (colg     > rAg) c[nt][0] = -1e30f;
                if (colg + 1 > rAg) c[nt][1] = -1e30f;
                if (colg     > rBg) c[nt][2] = -1e30f;
                if (colg + 1 > rBg) c[nt][3] = -1e30f;
            }
        }

        float tmA = -1e30f, tmB = -1e30f;
        #pragma unroll
        for (int nt = 0; nt < 8; nt++) {
            tmA = fmaxf(tmA, fmaxf(c[nt][0], c[nt][1]));
            tmB = fmaxf(tmB, fmaxf(c[nt][2], c[nt][3]));
        }
        tmA = fmaxf(tmA, __shfl_xor_sync(0xffffffffu, tmA, 1));
        tmA = fmaxf(tmA, __shfl_xor_sync(0xffffffffu, tmA, 2));
        tmB = fmaxf(tmB, __shfl_xor_sync(0xffffffffu, tmB, 1));
        tmB = fmaxf(tmB, __shfl_xor_sync(0xffffffffu, tmB, 2));

        const float mnA = fmaxf(mA, tmA), mnB = fmaxf(mB, tmB);
        const float alA = __expf(mA - mnA), alB = __expf(mB - mnB);
        mA = mnA; mB = mnB;

        float sA = 0.0f, sB = 0.0f;
        #pragma unroll
        for (int nt = 0; nt < 8; nt++) {
            c[nt][0] = __expf(c[nt][0] - mnA); sA += c[nt][0];
            c[nt][1] = __expf(c[nt][1] - mnA); sA += c[nt][1];
            c[nt][2] = __expf(c[nt][2] - mnB); sB += c[nt][2];
            c[nt][3] = __expf(c[nt][3] - mnB); sB += c[nt][3];
        }
        sA += __shfl_xor_sync(0xffffffffu, sA, 1);
        sA += __shfl_xor_sync(0xffffffffu, sA, 2);
        sB += __shfl_xor_sync(0xffffffffu, sB, 1);
        sB += __shfl_xor_sync(0xffffffffu, sB, 2);
        lA = lA * alA + sA;
        lB = lB * alB + sB;
        #pragma unroll
        for (int nt = 0; nt < 8; nt++) {
            o[nt][0] *= alA; o[nt][1] *= alA;
            o[nt][2] *= alB; o[nt][3] *= alB;
        }

        #pragma unroll
        for (int ks = 0; ks < 4; ks++) {
            uint32_t pH[4], pL[4];
            split2h(c[2*ks][0],     c[2*ks][1],     pH[0], pL[0]);
            split2h(c[2*ks][2],     c[2*ks][3],     pH[1], pL[1]);
            split2h(c[2*ks + 1][0], c[2*ks + 1][1], pH[2], pL[2]);
            split2h(c[2*ks + 1][2], c[2*ks + 1][3], pH[3], pL[3]);
            #pragma unroll
            for (int pfd = 0; pfd < 4; pfd++) {
                uint32_t bH[4];
                uint32_t ba = sb + bBase + (uint32_t)pfd * 16 * FPITCH + ks * 32;
                LDSM4(bH[0], bH[1], bH[2], bH[3], ba + SVH);
                const int nd = pfd * 2;
                mma16816(o[nd],     pH, bH[0], bH[1]);
                mma16816(o[nd],     pL, bH[0], bH[1]);
                mma16816(o[nd + 1], pH, bH[2], bH[3]);
                mma16816(o[nd + 1], pL, bH[2], bH[3]);
            }
        }
    }

    const int b = bh >> 4, h = bh & 15;
    const float invA = 1.0f / lA, invB = 1.0f / lB;
    const size_t ybA = ((size_t)(b * Tt + qt * 128 + rowA)) * Cc + h * HDIM;
    const size_t ybB = ((size_t)(b * Tt + qt * 128 + rowB)) * Cc + h * HDIM;
    #pragma unroll
    for (int nt = 0; nt < 8; nt++) {
        const int d = nt * 8 + tg * 2;
        uint32_t hi, lo;
        split2h(o[nt][0] * invA, o[nt][1] * invA, hi, lo);
        *(uint32_t*)&g_yhi[ybA + d] = hi;
        *(uint32_t*)&g_ylo[ybA + d] = lo;
        split2h(o[nt][2] * invB, o[nt][3] * invB, hi, lo);
        *(uint32_t*)&g_yhi[ybB + d] = hi;
        *(uint32_t*)&g_ylo[ybB + d] = lo;
    }
}

// ---------------------------------------------------------------------------
extern "C" void kernel_launch(void* const* d_in, const int* in_sizes, int n_in,
                              void* d_out, int out_size)
{
    (void)in_sizes; (void)n_in; (void)out_size;
    const float* x   = (const float*)d_in[0];
    const float* ipw = (const float*)d_in[1];
    const float* ipb = (const float*)d_in[2];
    const float* opw = (const float*)d_in[3];
    const float* opb = (const float*)d_in[4];
    float* out = (float*)d_out;

    cudaFuncSetAttribute(gemm_fp16x2<0>,
                         cudaFuncAttributeMaxDynamicSharedMemorySize, GEMM_SMEM);
    cudaFuncSetAttribute(gemm_fp16x2<1>,
                         cudaFuncAttributeMaxDynamicSharedMemorySize, GEMM_SMEM);
    cudaFuncSetAttribute(flash_attn_kernel,
                         cudaFuncAttributeMaxDynamicSharedMemorySize, FL_SMEM);

    // 0) fp16 conversions: x -> hi/lo, weights -> single fp16
    cvt_kernel<0><<<(Mm*Cc/4 + 255)/256, 256>>>(x,   Mm*Cc/4);
    cvt_kernel<1><<<(N1*Cc/4 + 255)/256, 256>>>(ipw, N1*Cc/4);
    cvt_kernel<2><<<(Cc*Cc/4 + 255)/256, 256>>>(opw, Cc*Cc/4);

    // 1) QKV projection + bias + fused RoPE -> Qhi/Qlo, Kh, Vt (fp16)
    {
        dim3 grid(N1 / 128, Mm / 128);
        gemm_fp16x2<0><<<grid, 256, GEMM_SMEM>>>(ipb, nullptr);
    }

    // 2) tensor-core causal flash attention (128-row q-tiles) -> g_yhi/g_ylo
    {
        dim3 grid(Tt / 128, BHt);   // (8, 128)
        flash_attn_kernel<<<grid, 256, FL_SMEM>>>();
    }

    // 3) output projection + bias
    {
        dim3 grid(Cc / 128, Mm / 128);
        gemm_fp16x2<1><<<grid, 256, GEMM_SMEM>>>(opb, out);
    }
}

// round 11
// speedup vs baseline: 1.6866x; 1.6866x over previous
#include <cuda_runtime.h>
#include <cuda_fp16.h>
#include <math.h>
#include <stdint.h>

#define Bb 8
#define Tt 1024
#define Cc 1024
#define NHEAD 16
#define HDIM 64
#define BHt (Bb*NHEAD)     // 128
#define Mm (Bb*Tt)         // 8192
#define N1 (3*Cc)          // 3072
#define KT 32              // 1024/32 k-tiles

// ------------------------- device scratch (no allocs allowed) --------------
__device__ __half g_xh [(size_t)Mm*Cc];
__device__ __half g_w1h[(size_t)N1*Cc];
__device__ __half g_w2h[(size_t)Cc*Cc];
__device__ __half g_yh [(size_t)Mm*Cc];
__device__ __half g_Qh [(size_t)BHt*Tt*HDIM];   // post-rope, x0.125
__device__ __half g_Kh [(size_t)BHt*Tt*HDIM];   // post-rope
__device__ __half g_Vth[(size_t)BHt*HDIM*Tt];   // [bh][d][t]

// ------------------------------ PTX helpers --------------------------------
__device__ __forceinline__ uint32_t smem_u32(const void* p) {
    uint32_t a;
    asm("{ .reg .u64 t; cvta.to.shared.u64 t, %1; cvt.u32.u64 %0, t; }"
        : "=r"(a) : "l"(p));
    return a;
}

#define CP16(dst, src) \
    asm volatile("cp.async.cg.shared.global [%0], [%1], 16;" \
                 :: "r"(dst), "l"(src) : "memory")
#define CP_COMMIT() asm volatile("cp.async.commit_group;" ::: "memory")
#define CP_WAIT1()  asm volatile("cp.async.wait_group 1;" ::: "memory")
#define CP_WAIT0()  asm volatile("cp.async.wait_group 0;" ::: "memory")

#define LDSM4(r0, r1, r2, r3, a) \
    asm volatile("ldmatrix.sync.aligned.m8n8.x4.shared.b16 {%0,%1,%2,%3}, [%4];" \
                 : "=r"(r0), "=r"(r1), "=r"(r2), "=r"(r3) : "r"(a))

__device__ __forceinline__ void mma16816(float c[4], const uint32_t a[4],
                                         uint32_t b0, uint32_t b1) {
    asm volatile("mma.sync.aligned.m16n8k16.row.col.f32.f16.f16.f32 "
                 "{%0,%1,%2,%3}, {%4,%5,%6,%7}, {%8,%9}, {%0,%1,%2,%3};"
                 : "+f"(c[0]), "+f"(c[1]), "+f"(c[2]), "+f"(c[3])
                 : "r"(a[0]), "r"(a[1]), "r"(a[2]), "r"(a[3]),
                   "r"(b0), "r"(b1));
}

__device__ __forceinline__ uint32_t pack2h(float x, float y) {
    __half2 h = __floats2half2_rn(x, y);
    return *reinterpret_cast<uint32_t*>(&h);
}

// ---------------------------------------------------------------------------
// fp32 -> fp16 conversion (single).  W=0: x.  W=1: w1.  W=2: w2.
// ---------------------------------------------------------------------------
template<int W>
__global__ __launch_bounds__(256)
void cvt_kernel(const float* __restrict__ src, int n4)
{
    int i = blockIdx.x * blockDim.x + threadIdx.x;
    if (i >= n4) return;
    float4 v = ((const float4*)src)[i];
    uint2 o = make_uint2(pack2h(v.x, v.y), pack2h(v.z, v.w));
    if (W == 0)      ((uint2*)g_xh)[i]  = o;
    else if (W == 1) ((uint2*)g_w1h)[i] = o;
    else             ((uint2*)g_w2h)[i] = o;
}

// ---------------------------------------------------------------------------
// fp16 NT GEMM via mma.sync: 128x128 block, 256 thr, 8 warps (2x4, 64x32).
// Single-term: 16 MMAs per kk pass. Double-buffered cp.async, 80B pitch.
// MODE 0: qkv = x @ w1^T + b, fused RoPE epilogue.  MODE 1: y @ w2^T + b.
// ---------------------------------------------------------------------------
#define T_AH 0
#define T_BH 10240
#define STAGE_BYTES 20480
#define GEMM_SMEM (2*STAGE_BYTES)

#define ROPE_LN_OVER_32 0.2878231366242557f   // ln(10000)/32

__device__ __forceinline__ void gemm_prefetch(uint32_t sdst,
    const __half* a_h, const __half* b_h)
{
    CP16(sdst + T_AH,      a_h);
    CP16(sdst + T_AH + 16, a_h + 8);
    CP16(sdst + T_BH,      b_h);
    CP16(sdst + T_BH + 16, b_h + 8);
}

// Epilogue scatter with fused RoPE. v = (col d, col d+1), d even.
__device__ __forceinline__ void scatter_qkv(int m, int n, float2 v)
{
    const int which = n >> 10, c = n & 1023;
    const int h = c >> 6, d = c & 63;
    const int b = m >> 10, t = m & 1023, bh = b * NHEAD + h;
    if (which == 2) {
        size_t i0 = ((size_t)bh * HDIM + d) * Tt + t;
        g_Vth[i0]      = __float2half(v.x);
        g_Vth[i0 + Tt] = __float2half(v.y);
        return;
    }
    const float inv = expf(-(float)(d >> 1) * ROPE_LN_OVER_32);
    float sv, cv;
    sincosf((float)t * inv, &sv, &cv);
    float r1 = v.x * cv - v.y * sv;
    float r2 = v.y * cv + v.x * sv;
    const size_t base = ((size_t)bh * Tt + t) * HDIM + d;
    if (which == 0) {
        *(uint32_t*)&g_Qh[base] = pack2h(r1 * 0.125f, r2 * 0.125f);
    } else {
        *(uint32_t*)&g_Kh[base] = pack2h(r1, r2);
    }
}

template<int MODE>
__global__ __launch_bounds__(256)
void gemm_fp16(const float* __restrict__ bias, float* __restrict__ Cout)
{
    extern __shared__ char smem[];
    const uint32_t sb = smem_u32(smem);
    const int tid  = threadIdx.x;
    const int lane = tid & 31, wid = tid >> 5;
    const int wm = wid >> 2, wn = wid & 3;         // 2 x 4 warp grid, 64x32 tiles
    const int m0 = blockIdx.y * 128, n0 = blockIdx.x * 128;

    const __half* Ah = (MODE == 0) ? g_xh  : g_yh;
    const __half* Bh = (MODE == 0) ? g_w1h : g_w2h;

    const int lr = tid >> 1;
    const int lh = tid & 1;
    const size_t gA = (size_t)(m0 + lr) * Cc + lh * 16;
    const size_t gB = (size_t)(n0 + lr) * Cc + lh * 16;
    const uint32_t sOff = (uint32_t)lr * 80 + lh * 32;

    const int jq = lane >> 3, rr = lane & 7;
    const int aRow  = wm * 64 + (jq & 1) * 8 + rr;
    const int aColB = (jq >> 1) * 16;
    const int bRow  = wn * 32 + (jq >> 1) * 8 + rr;
    const int bColB = (jq & 1) * 16;

    float acc[4][4][4];
    #pragma unroll
    for (int i = 0; i < 4; i++)
        #pragma unroll
        for (int j = 0; j < 4; j++)
            #pragma unroll
            for (int e = 0; e < 4; e++) acc[i][j][e] = 0.0f;

    gemm_prefetch(sb + sOff, Ah + gA, Bh + gB);
    CP_COMMIT();

    for (int kt = 0; kt < KT; kt++) {
        const int cur = kt & 1;
        if (kt + 1 < KT) {
            const size_t ko = (size_t)(kt + 1) * 32;
            gemm_prefetch(sb + ((kt + 1) & 1) * STAGE_BYTES + sOff,
                          Ah + gA + ko, Bh + gB + ko);
            CP_COMMIT();
            CP_WAIT1();
        } else {
            CP_WAIT0();
        }
        __syncthreads();

        const uint32_t base = sb + cur * STAGE_BYTES;
        #pragma unroll
        for (int kk = 0; kk < 2; kk++) {
            const uint32_t kB = kk * 32;
            uint32_t ah[4][4], bh[2][4];
            #pragma unroll
            for (int mf = 0; mf < 4; mf++) {
                uint32_t addr = base + (uint32_t)(aRow + mf * 16) * 80 + aColB + kB;
                LDSM4(ah[mf][0], ah[mf][1], ah[mf][2], ah[mf][3], addr + T_AH);
            }
            #pragma unroll
            for (int pf = 0; pf < 2; pf++) {
                uint32_t addr = base + (uint32_t)(bRow + pf * 16) * 80 + bColB + kB;
                LDSM4(bh[pf][0], bh[pf][1], bh[pf][2], bh[pf][3], addr + T_BH);
            }
            #pragma unroll
            for (int mf = 0; mf < 4; mf++) {
                #pragma unroll
                for (int nt = 0; nt < 4; nt++) {
                    const int pf = nt >> 1, ix = (nt & 1) * 2;
                    mma16816(acc[mf][nt], ah[mf], bh[pf][ix], bh[pf][ix + 1]);
                }
            }
        }
        __syncthreads();
    }

    const int gid = lane >> 2, tg = lane & 3;
    #pragma unroll
    for (int mf = 0; mf < 4; mf++) {
        #pragma unroll
        for (int nt = 0; nt < 4; nt++) {
            const int n = n0 + wn * 32 + nt * 8 + tg * 2;
            const float2 bv = *(const float2*)&bias[n];
            const int mA = m0 + wm * 64 + mf * 16 + gid;
            float2 v01 = make_float2(acc[mf][nt][0] + bv.x, acc[mf][nt][1] + bv.y);
            float2 v23 = make_float2(acc[mf][nt][2] + bv.x, acc[mf][nt][3] + bv.y);
            if (MODE == 0) {
                scatter_qkv(mA,     n, v01);
                scatter_qkv(mA + 8, n, v23);
            } else {
                *(float2*)&Cout[(size_t)mA * Cc + n]       = v01;
                *(float2*)&Cout[(size_t)(mA + 8) * Cc + n] = v23;
            }
        }
    }
}

// ---------------------------------------------------------------------------
// Tensor-core flash attention (fp16), causal. Block = (qt, bh), 128 thr.
// Single-term: 32 MMAs per kt for S, 32 for PV.
// Smem: Qh Kh Vh, 64x72 fp16 tiles (pitch 144B).
// ---------------------------------------------------------------------------
#define FPITCH 144
#define SQH 0
#define SKH 9216
#define SVH 18432
#define FL_SMEM 27648

__global__ __launch_bounds__(128)
void flash_attn_kernel()
{
    extern __shared__ char smem[];
    const uint32_t sb = smem_u32(smem);
    const int tid  = threadIdx.x;
    const int lane = tid & 31, w = tid >> 5;
    const int qt = blockIdx.x;     // 0..15
    const int bh = blockIdx.y;     // 0..127

    const __half* Qh = g_Qh  + ((size_t)bh * Tt + qt * 64) * HDIM;
    const __half* Kh = g_Kh  + (size_t)bh * Tt * HDIM;
    const __half* Vh = g_Vth + (size_t)bh * HDIM * Tt;

    #pragma unroll
    for (int ii = 0; ii < 4; ii++) {
        int idx = tid + 128 * ii;
        int r = idx >> 3, c8 = (idx & 7) * 8;
        uint32_t so = (uint32_t)r * FPITCH + c8 * 2;
        *(uint4*)(smem + SQH + so) = *(const uint4*)&Qh[r * 64 + c8];
    }

    const int jq = lane >> 3, rr = lane & 7;
    const uint32_t aAddr = sb + (uint32_t)(w * 16 + (lane & 15)) * FPITCH
                         + (lane >> 4) * 16;
    const uint32_t bBase = (uint32_t)((jq >> 1) * 8 + rr) * FPITCH
                         + (jq & 1) * 16;

    const int gid = lane >> 2, tg = lane & 3;
    const int rowA = w * 16 + gid;
    const int rowB = rowA + 8;

    float o[8][4];
    #pragma unroll
    for (int nt = 0; nt < 8; nt++)
        #pragma unroll
        for (int e = 0; e < 4; e++) o[nt][e] = 0.0f;
    float mA = -1e30f, mB = -1e30f, lA = 0.0f, lB = 0.0f;

    for (int kt = 0; kt <= qt; kt++) {
        __syncthreads();
        #pragma unroll
        for (int ii = 0; ii < 4; ii++) {
            int idx = tid + 128 * ii;
            int r = idx >> 3, c8 = (idx & 7) * 8;
            uint32_t so = (uint32_t)r * FPITCH + c8 * 2;
            *(uint4*)(smem + SKH + so) = *(const uint4*)&Kh[(kt * 64 + r) * 64 + c8];
            *(uint4*)(smem + SVH + so) = *(const uint4*)&Vh[(size_t)r * Tt + kt * 64 + c8];
        }
        __syncthreads();

        float c[8][4];
        #pragma unroll
        for (int nt = 0; nt < 8; nt++)
            #pragma unroll
            for (int e = 0; e < 4; e++) c[nt][e] = 0.0f;

        #pragma unroll
        for (int kk = 0; kk < 4; kk++) {
            uint32_t aH[4];
            LDSM4(aH[0], aH[1], aH[2], aH[3], aAddr + SQH + kk * 32);
            #pragma unroll
            for (int pf = 0; pf < 4; pf++) {
                uint32_t bH[4];
                uint32_t ba = sb + bBase + (uint32_t)pf * 16 * FPITCH + kk * 32;
                LDSM4(bH[0], bH[1], bH[2], bH[3], ba + SKH);
                const int nt0 = pf * 2;
                mma16816(c[nt0],     aH, bH[0], bH[1]);
                mma16816(c[nt0 + 1], aH, bH[2], bH[3]);
            }
        }

        if (kt == qt) {
            #pragma unroll
            for (int nt = 0; nt < 8; nt++) {
                const int colb = nt * 8 + tg * 2;
                if (colb     > rowA) c[nt][0] = -1e30f;
                if (colb + 1 > rowA) c[nt][1] = -1e30f;
                if (colb     > rowB) c[nt][2] = -1e30f;
                if (colb + 1 > rowB) c[nt][3] = -1e30f;
            }
        }

        float tmA = -1e30f, tmB = -1e30f;
        #pragma unroll
        for (int nt = 0; nt < 8; nt++) {
            tmA = fmaxf(tmA, fmaxf(c[nt][0], c[nt][1]));
            tmB = fmaxf(tmB, fmaxf(c[nt][2], c[nt][3]));
        }
        tmA = fmaxf(tmA, __shfl_xor_sync(0xffffffffu, tmA, 1));
        tmA = fmaxf(tmA, __shfl_xor_sync(0xffffffffu, tmA, 2));
        tmB = fmaxf(tmB, __shfl_xor_sync(0xffffffffu, tmB, 1));
        tmB = fmaxf(tmB, __shfl_xor_sync(0xffffffffu, tmB, 2));

        const float mnA = fmaxf(mA, tmA), mnB = fmaxf(mB, tmB);
        const float alA = __expf(mA - mnA), alB = __expf(mB - mnB);
        mA = mnA; mB = mnB;

        float sA = 0.0f, sB = 0.0f;
        #pragma unroll
        for (int nt = 0; nt < 8; nt++) {
            c[nt][0] = __expf(c[nt][0] - mnA); sA += c[nt][0];
            c[nt][1] = __expf(c[nt][1] - mnA); sA += c[nt][1];
            c[nt][2] = __expf(c[nt][2] - mnB); sB += c[nt][2];
            c[nt][3] = __expf(c[nt][3] - mnB); sB += c[nt][3];
        }
        sA += __shfl_xor_sync(0xffffffffu, sA, 1);
        sA += __shfl_xor_sync(0xffffffffu, sA, 2);
        sB += __shfl_xor_sync(0xffffffffu, sB, 1);
        sB += __shfl_xor_sync(0xffffffffu, sB, 2);
        lA = lA * alA + sA;
        lB = lB * alB + sB;
        #pragma unroll
        for (int nt = 0; nt < 8; nt++) {
            o[nt][0] *= alA; o[nt][1] *= alA;
            o[nt][2] *= alB; o[nt][3] *= alB;
        }

        #pragma unroll
        for (int ks = 0; ks < 4; ks++) {
            uint32_t pH[4];
            pH[0] = pack2h(c[2*ks][0],     c[2*ks][1]);
            pH[1] = pack2h(c[2*ks][2],     c[2*ks][3]);
            pH[2] = pack2h(c[2*ks + 1][0], c[2*ks + 1][1]);
            pH[3] = pack2h(c[2*ks + 1][2], c[2*ks + 1][3]);
            #pragma unroll
            for (int pfd = 0; pfd < 4; pfd++) {
                uint32_t bH[4];
                uint32_t ba = sb + bBase + (uint32_t)pfd * 16 * FPITCH + ks * 32;
                LDSM4(bH[0], bH[1], bH[2], bH[3], ba + SVH);
                const int nd = pfd * 2;
                mma16816(o[nd],     pH, bH[0], bH[1]);
                mma16816(o[nd + 1], pH, bH[2], bH[3]);
            }
        }
    }

    const int b = bh >> 4, h = bh & 15;
    const float invA = 1.0f / lA, invB = 1.0f / lB;
    const size_t ybA = ((size_t)(b * Tt + qt * 64 + rowA)) * Cc + h * HDIM;
    const size_t ybB = ((size_t)(b * Tt + qt * 64 + rowB)) * Cc + h * HDIM;
    #pragma unroll
    for (int nt = 0; nt < 8; nt++) {
        const int d = nt * 8 + tg * 2;
        *(uint32_t*)&g_yh[ybA + d] = pack2h(o[nt][0] * invA, o[nt][1] * invA);
        *(uint32_t*)&g_yh[ybB + d] = pack2h(o[nt][2] * invB, o[nt][3] * invB);
    }
}

// ---------------------------------------------------------------------------
extern "C" void kernel_launch(void* const* d_in, const int* in_sizes, int n_in,
                              void* d_out, int out_size)
{
    (void)in_sizes; (void)n_in; (void)out_size;
    const float* x   = (const float*)d_in[0];
    const float* ipw = (const float*)d_in[1];
    const float* ipb = (const float*)d_in[2];
    const float* opw = (const float*)d_in[3];
    const float* opb = (const float*)d_in[4];
    float* out = (float*)d_out;

    cudaFuncSetAttribute(gemm_fp16<0>,
                         cudaFuncAttributeMaxDynamicSharedMemorySize, GEMM_SMEM);
    cudaFuncSetAttribute(gemm_fp16<1>,
                         cudaFuncAttributeMaxDynamicSharedMemorySize, GEMM_SMEM);
    cudaFuncSetAttribute(flash_attn_kernel,
                         cudaFuncAttributeMaxDynamicSharedMemorySize, FL_SMEM);

    // 0) fp16 conversions
    cvt_kernel<0><<<(Mm*Cc/4 + 255)/256, 256>>>(x,   Mm*Cc/4);
    cvt_kernel<1><<<(N1*Cc/4 + 255)/256, 256>>>(ipw, N1*Cc/4);
    cvt_kernel<2><<<(Cc*Cc/4 + 255)/256, 256>>>(opw, Cc*Cc/4);

    // 1) QKV projection + bias + fused RoPE -> Qh, Kh, Vt (fp16)
    {
        dim3 grid(N1 / 128, Mm / 128);
        gemm_fp16<0><<<grid, 256, GEMM_SMEM>>>(ipb, nullptr);
    }

    // 2) tensor-core causal flash attention -> g_yh
    {
        dim3 grid(Tt / 64, BHt);
        flash_attn_kernel<<<grid, 128, FL_SMEM>>>();
    }

    // 3) output projection + bias
    {
        dim3 grid(Cc / 128, Mm / 128);
        gemm_fp16<1><<<grid, 256, GEMM_SMEM>>>(opb, out);
    }
}

// round 12
// speedup vs baseline: 1.7996x; 1.0670x over previous
#include <cuda_runtime.h>
#include <cuda_fp16.h>
#include <math.h>
#include <stdint.h>

#define Bb 8
#define Tt 1024
#define Cc 1024
#define NHEAD 16
#define HDIM 64
#define BHt (Bb*NHEAD)     // 128
#define Mm (Bb*Tt)         // 8192
#define N1 (3*Cc)          // 3072
#define KT 32              // 1024/32 k-tiles

// ------------------------- device scratch (no allocs allowed) --------------
__device__ __half g_xh [(size_t)Mm*Cc];
__device__ __half g_w1h[(size_t)N1*Cc];
__device__ __half g_w2h[(size_t)Cc*Cc];
__device__ __half g_yh [(size_t)Mm*Cc];
__device__ __half g_Qh [(size_t)BHt*Tt*HDIM];   // post-rope, x0.125
__device__ __half g_Kh [(size_t)BHt*Tt*HDIM];   // post-rope
__device__ __half g_Vth[(size_t)BHt*HDIM*Tt];   // [bh][d][t]

// ------------------------------ PTX helpers --------------------------------
__device__ __forceinline__ uint32_t smem_u32(const void* p) {
    uint32_t a;
    asm("{ .reg .u64 t; cvta.to.shared.u64 t, %1; cvt.u32.u64 %0, t; }"
        : "=r"(a) : "l"(p));
    return a;
}

#define CP16(dst, src) \
    asm volatile("cp.async.cg.shared.global [%0], [%1], 16;" \
                 :: "r"(dst), "l"(src) : "memory")
#define CP_COMMIT() asm volatile("cp.async.commit_group;" ::: "memory")
#define CP_WAIT0()  asm volatile("cp.async.wait_group 0;" ::: "memory")

#define LDSM4(r0, r1, r2, r3, a) \
    asm volatile("ldmatrix.sync.aligned.m8n8.x4.shared.b16 {%0,%1,%2,%3}, [%4];" \
                 : "=r"(r0), "=r"(r1), "=r"(r2), "=r"(r3) : "r"(a))

__device__ __forceinline__ void mma16816(float c[4], const uint32_t a[4],
                                         uint32_t b0, uint32_t b1) {
    asm volatile("mma.sync.aligned.m16n8k16.row.col.f32.f16.f16.f32 "
                 "{%0,%1,%2,%3}, {%4,%5,%6,%7}, {%8,%9}, {%0,%1,%2,%3};"
                 : "+f"(c[0]), "+f"(c[1]), "+f"(c[2]), "+f"(c[3])
                 : "r"(a[0]), "r"(a[1]), "r"(a[2]), "r"(a[3]),
                   "r"(b0), "r"(b1));
}

__device__ __forceinline__ uint32_t pack2h(float x, float y) {
    __half2 h = __floats2half2_rn(x, y);
    return *reinterpret_cast<uint32_t*>(&h);
}

// ---------------------------------------------------------------------------
// fp32 -> fp16 conversion (single).  W=0: x.  W=1: w1.  W=2: w2.
// ---------------------------------------------------------------------------
template<int W>
__global__ __launch_bounds__(256)
void cvt_kernel(const float* __restrict__ src, int n4)
{
    int i = blockIdx.x * blockDim.x + threadIdx.x;
    if (i >= n4) return;
    float4 v = ((const float4*)src)[i];
    uint2 o = make_uint2(pack2h(v.x, v.y), pack2h(v.z, v.w));
    if (W == 0)      ((uint2*)g_xh)[i]  = o;
    else if (W == 1) ((uint2*)g_w1h)[i] = o;
    else             ((uint2*)g_w2h)[i] = o;
}

// ---------------------------------------------------------------------------
// fp16 NT GEMM via mma.sync: 128x128 block, 256 thr, 8 warps (2x4, 64x32).
// Single sync per k-tile: wait<0>; sync; prefetch(kt+1); compute(kt).
// MODE 0: qkv = x @ w1^T + b, fused RoPE epilogue.  MODE 1: y @ w2^T + b.
// ---------------------------------------------------------------------------
#define T_AH 0
#define T_BH 10240
#define STAGE_BYTES 20480
#define GEMM_SMEM (2*STAGE_BYTES)

#define ROPE_LN_OVER_32 0.2878231366242557f   // ln(10000)/32

__device__ __forceinline__ void gemm_prefetch(uint32_t sdst,
    const __half* a_h, const __half* b_h)
{
    CP16(sdst + T_AH,      a_h);
    CP16(sdst + T_AH + 16, a_h + 8);
    CP16(sdst + T_BH,      b_h);
    CP16(sdst + T_BH + 16, b_h + 8);
}

// Epilogue scatter with fused RoPE. v = (col d, col d+1), d even.
__device__ __forceinline__ void scatter_qkv(int m, int n, float2 v)
{
    const int which = n >> 10, c = n & 1023;
    const int h = c >> 6, d = c & 63;
    const int b = m >> 10, t = m & 1023, bh = b * NHEAD + h;
    if (which == 2) {
        size_t i0 = ((size_t)bh * HDIM + d) * Tt + t;
        g_Vth[i0]      = __float2half(v.x);
        g_Vth[i0 + Tt] = __float2half(v.y);
        return;
    }
    const float inv = expf(-(float)(d >> 1) * ROPE_LN_OVER_32);
    float sv, cv;
    sincosf((float)t * inv, &sv, &cv);
    float r1 = v.x * cv - v.y * sv;
    float r2 = v.y * cv + v.x * sv;
    const size_t base = ((size_t)bh * Tt + t) * HDIM + d;
    if (which == 0) {
        *(uint32_t*)&g_Qh[base] = pack2h(r1 * 0.125f, r2 * 0.125f);
    } else {
        *(uint32_t*)&g_Kh[base] = pack2h(r1, r2);
    }
}

template<int MODE>
__global__ __launch_bounds__(256)
void gemm_fp16(const float* __restrict__ bias, float* __restrict__ Cout)
{
    extern __shared__ char smem[];
    const uint32_t sb = smem_u32(smem);
    const int tid  = threadIdx.x;
    const int lane = tid & 31, wid = tid >> 5;
    const int wm = wid >> 2, wn = wid & 3;         // 2 x 4 warp grid, 64x32 tiles
    const int m0 = blockIdx.y * 128, n0 = blockIdx.x * 128;

    const __half* Ah = (MODE == 0) ? g_xh  : g_yh;
    const __half* Bh = (MODE == 0) ? g_w1h : g_w2h;

    const int lr = tid >> 1;
    const int lh = tid & 1;
    const size_t gA = (size_t)(m0 + lr) * Cc + lh * 16;
    const size_t gB = (size_t)(n0 + lr) * Cc + lh * 16;
    const uint32_t sOff = (uint32_t)lr * 80 + lh * 32;

    const int jq = lane >> 3, rr = lane & 7;
    const int aRow  = wm * 64 + (jq & 1) * 8 + rr;
    const int aColB = (jq >> 1) * 16;
    const int bRow  = wn * 32 + (jq >> 1) * 8 + rr;
    const int bColB = (jq & 1) * 16;

    float acc[4][4][4];
    #pragma unroll
    for (int i = 0; i < 4; i++)
        #pragma unroll
        for (int j = 0; j < 4; j++)
            #pragma unroll
            for (int e = 0; e < 4; e++) acc[i][j][e] = 0.0f;

    gemm_prefetch(sb + sOff, Ah + gA, Bh + gB);
    CP_COMMIT();

    for (int kt = 0; kt < KT; kt++) {
        CP_WAIT0();
        __syncthreads();           // stage kt visible; stage (kt+1)&1 free
        if (kt + 1 < KT) {
            const size_t ko = (size_t)(kt + 1) * 32;
            gemm_prefetch(sb + ((kt + 1) & 1) * STAGE_BYTES + sOff,
                          Ah + gA + ko, Bh + gB + ko);
            CP_COMMIT();
        }

        const uint32_t base = sb + (kt & 1) * STAGE_BYTES;
        #pragma unroll
        for (int kk = 0; kk < 2; kk++) {
            const uint32_t kB = kk * 32;
            uint32_t ah[4][4], bh[2][4];
            #pragma unroll
            for (int mf = 0; mf < 4; mf++) {
                uint32_t addr = base + (uint32_t)(aRow + mf * 16) * 80 + aColB + kB;
                LDSM4(ah[mf][0], ah[mf][1], ah[mf][2], ah[mf][3], addr + T_AH);
            }
            #pragma unroll
            for (int pf = 0; pf < 2; pf++) {
                uint32_t addr = base + (uint32_t)(bRow + pf * 16) * 80 + bColB + kB;
                LDSM4(bh[pf][0], bh[pf][1], bh[pf][2], bh[pf][3], addr + T_BH);
            }
            #pragma unroll
            for (int mf = 0; mf < 4; mf++) {
                #pragma unroll
                for (int nt = 0; nt < 4; nt++) {
                    const int pf = nt >> 1, ix = (nt & 1) * 2;
                    mma16816(acc[mf][nt], ah[mf], bh[pf][ix], bh[pf][ix + 1]);
                }
            }
        }
    }

    const int gid = lane >> 2, tg = lane & 3;
    #pragma unroll
    for (int mf = 0; mf < 4; mf++) {
        #pragma unroll
        for (int nt = 0; nt < 4; nt++) {
            const int n = n0 + wn * 32 + nt * 8 + tg * 2;
            const float2 bv = *(const float2*)&bias[n];
            const int mA = m0 + wm * 64 + mf * 16 + gid;
            float2 v01 = make_float2(acc[mf][nt][0] + bv.x, acc[mf][nt][1] + bv.y);
            float2 v23 = make_float2(acc[mf][nt][2] + bv.x, acc[mf][nt][3] + bv.y);
            if (MODE == 0) {
                scatter_qkv(mA,     n, v01);
                scatter_qkv(mA + 8, n, v23);
            } else {
                *(float2*)&Cout[(size_t)mA * Cc + n]       = v01;
                *(float2*)&Cout[(size_t)(mA + 8) * Cc + n] = v23;
            }
        }
    }
}

// ---------------------------------------------------------------------------
// Tensor-core flash attention (fp16), causal. Block = (qt, bh), 128 thr.
// K/V double-buffered via cp.async; single sync per k-tile; loads overlap MMA.
// Smem: Qh (9216) + 2 x (Kh 9216 + Vh 9216) = 46080 B, pitch 144B.
// ---------------------------------------------------------------------------
#define FPITCH 144
#define SQH 0
#define SKV0 9216
#define KV_STAGE 18432
#define FL_SMEM 46080

__global__ __launch_bounds__(128)
void flash_attn_kernel()
{
    extern __shared__ char smem[];
    const uint32_t sb = smem_u32(smem);
    const int tid  = threadIdx.x;
    const int lane = tid & 31, w = tid >> 5;
    const int qt = blockIdx.x;     // 0..15
    const int bh = blockIdx.y;     // 0..127

    const __half* Qh = g_Qh  + ((size_t)bh * Tt + qt * 64) * HDIM;
    const __half* Kh = g_Kh  + (size_t)bh * Tt * HDIM;
    const __half* Vh = g_Vth + (size_t)bh * HDIM * Tt;

    // per-thread K/V prefetch geometry: 4 pieces each of K and V per stage
    const int pr  = tid >> 1;              // 0..63 row pairs? -> use idx scheme
    (void)pr;

    // Q tile load (plain, once)
    #pragma unroll
    for (int ii = 0; ii < 4; ii++) {
        int idx = tid + 128 * ii;
        int r = idx >> 3, c8 = (idx & 7) * 8;
        uint32_t so = (uint32_t)r * FPITCH + c8 * 2;
        *(uint4*)(smem + SQH + so) = *(const uint4*)&Qh[r * 64 + c8];
    }

    const int jq = lane >> 3, rr = lane & 7;
    const uint32_t aAddr = sb + (uint32_t)(w * 16 + (lane & 15)) * FPITCH
                         + (lane >> 4) * 16;
    const uint32_t bBase = (uint32_t)((jq >> 1) * 8 + rr) * FPITCH
                         + (jq & 1) * 16;

    const int gid = lane >> 2, tg = lane & 3;
    const int rowA = w * 16 + gid;
    const int rowB = rowA + 8;

    float o[8][4];
    #pragma unroll
    for (int nt = 0; nt < 8; nt++)
        #pragma unroll
        for (int e = 0; e < 4; e++) o[nt][e] = 0.0f;
    float mA = -1e30f, mB = -1e30f, lA = 0.0f, lB = 0.0f;

    // prologue: prefetch kt=0 into stage 0
    #pragma unroll
    for (int ii = 0; ii < 4; ii++) {
        int idx = tid + 128 * ii;
        int r = idx >> 3, c8 = (idx & 7) * 8;
        uint32_t so = (uint32_t)r * FPITCH + c8 * 2;
        CP16(sb + SKV0 + so,        &Kh[(size_t)r * 64 + c8]);
        CP16(sb + SKV0 + 9216 + so, &Vh[(size_t)r * Tt + c8]);
    }
    CP_COMMIT();

    for (int kt = 0; kt <= qt; kt++) {
        CP_WAIT0();
        __syncthreads();          // stage kt&1 ready + other stage free
        if (kt < qt) {
            const uint32_t sdst = sb + SKV0 + ((kt + 1) & 1) * KV_STAGE;
            #pragma unroll
            for (int ii = 0; ii < 4; ii++) {
                int idx = tid + 128 * ii;
                int r = idx >> 3, c8 = (idx & 7) * 8;
                uint32_t so = (uint32_t)r * FPITCH + c8 * 2;
                CP16(sdst + so,        &Kh[((kt + 1) * 64 + r) * 64 + c8]);
                CP16(sdst + 9216 + so, &Vh[(size_t)r * Tt + (kt + 1) * 64 + c8]);
            }
            CP_COMMIT();
        }

        const uint32_t kvb = sb + SKV0 + (kt & 1) * KV_STAGE;

        float c[8][4];
        #pragma unroll
        for (int nt = 0; nt < 8; nt++)
            #pragma unroll
            for (int e = 0; e < 4; e++) c[nt][e] = 0.0f;

        #pragma unroll
        for (int kk = 0; kk < 4; kk++) {
            uint32_t aH[4];
            LDSM4(aH[0], aH[1], aH[2], aH[3], aAddr + SQH + kk * 32);
            #pragma unroll
            for (int pf = 0; pf < 4; pf++) {
                uint32_t bH[4];
                uint32_t ba = kvb + bBase + (uint32_t)pf * 16 * FPITCH + kk * 32;
                LDSM4(bH[0], bH[1], bH[2], bH[3], ba);
                const int nt0 = pf * 2;
                mma16816(c[nt0],     aH, bH[0], bH[1]);
                mma16816(c[nt0 + 1], aH, bH[2], bH[3]);
            }
        }

        if (kt == qt) {
            #pragma unroll
            for (int nt = 0; nt < 8; nt++) {
                const int colb = nt * 8 + tg * 2;
                if (colb     > rowA) c[nt][0] = -1e30f;
                if (colb + 1 > rowA) c[nt][1] = -1e30f;
                if (colb     > rowB) c[nt][2] = -1e30f;
                if (colb + 1 > rowB) c[nt][3] = -1e30f;
            }
        }

        float tmA = -1e30f, tmB = -1e30f;
        #pragma unroll
        for (int nt = 0; nt < 8; nt++) {
            tmA = fmaxf(tmA, fmaxf(c[nt][0], c[nt][1]));
            tmB = fmaxf(tmB, fmaxf(c[nt][2], c[nt][3]));
        }
        tmA = fmaxf(tmA, __shfl_xor_sync(0xffffffffu, tmA, 1));
        tmA = fmaxf(tmA, __shfl_xor_sync(0xffffffffu, tmA, 2));
        tmB = fmaxf(tmB, __shfl_xor_sync(0xffffffffu, tmB, 1));
        tmB = fmaxf(tmB, __shfl_xor_sync(0xffffffffu, tmB, 2));

        const float mnA = fmaxf(mA, tmA), mnB = fmaxf(mB, tmB);
        const float alA = __expf(mA - mnA), alB = __expf(mB - mnB);
        mA = mnA; mB = mnB;

        float sA = 0.0f, sB = 0.0f;
        #pragma unroll
        for (int nt = 0; nt < 8; nt++) {
            c[nt][0] = __expf(c[nt][0] - mnA); sA += c[nt][0];
            c[nt][1] = __expf(c[nt][1] - mnA); sA += c[nt][1];
            c[nt][2] = __expf(c[nt][2] - mnB); sB += c[nt][2];
            c[nt][3] = __expf(c[nt][3] - mnB); sB += c[nt][3];
        }
        sA += __shfl_xor_sync(0xffffffffu, sA, 1);
        sA += __shfl_xor_sync(0xffffffffu, sA, 2);
        sB += __shfl_xor_sync(0xffffffffu, sB, 1);
        sB += __shfl_xor_sync(0xffffffffu, sB, 2);
        lA = lA * alA + sA;
        lB = lB * alB + sB;
        #pragma unroll
        for (int nt = 0; nt < 8; nt++) {
            o[nt][0] *= alA; o[nt][1] *= alA;
            o[nt][2] *= alB; o[nt][3] *= alB;
        }

        #pragma unroll
        for (int ks = 0; ks < 4; ks++) {
            uint32_t pH[4];
            pH[0] = pack2h(c[2*ks][0],     c[2*ks][1]);
            pH[1] = pack2h(c[2*ks][2],     c[2*ks][3]);
            pH[2] = pack2h(c[2*ks + 1][0], c[2*ks + 1][1]);
            pH[3] = pack2h(c[2*ks + 1][2], c[2*ks + 1][3]);
            #pragma unroll
            for (int pfd = 0; pfd < 4; pfd++) {
                uint32_t bH[4];
                uint32_t ba = kvb + 9216 + bBase + (uint32_t)pfd * 16 * FPITCH + ks * 32;
                LDSM4(bH[0], bH[1], bH[2], bH[3], ba);
                const int nd = pfd * 2;
                mma16816(o[nd],     pH, bH[0], bH[1]);
                mma16816(o[nd + 1], pH, bH[2], bH[3]);
            }
        }
    }

    const int b = bh >> 4, h = bh & 15;
    const float invA = 1.0f / lA, invB = 1.0f / lB;
    const size_t ybA = ((size_t)(b * Tt + qt * 64 + rowA)) * Cc + h * HDIM;
    const size_t ybB = ((size_t)(b * Tt + qt * 64 + rowB)) * Cc + h * HDIM;
    #pragma unroll
    for (int nt = 0; nt < 8; nt++) {
        const int d = nt * 8 + tg * 2;
        *(uint32_t*)&g_yh[ybA + d] = pack2h(o[nt][0] * invA, o[nt][1] * invA);
        *(uint32_t*)&g_yh[ybB + d] = pack2h(o[nt][2] * invB, o[nt][3] * invB);
    }
}

// ---------------------------------------------------------------------------
extern "C" void kernel_launch(void* const* d_in, const int* in_sizes, int n_in,
                              void* d_out, int out_size)
{
    (void)in_sizes; (void)n_in; (void)out_size;
    const float* x   = (const float*)d_in[0];
    const float* ipw = (const float*)d_in[1];
    const float* ipb = (const float*)d_in[2];
    const float* opw = (const float*)d_in[3];
    const float* opb = (const float*)d_in[4];
    float* out = (float*)d_out;

    cudaFuncSetAttribute(gemm_fp16<0>,
                         cudaFuncAttributeMaxDynamicSharedMemorySize, GEMM_SMEM);
    cudaFuncSetAttribute(gemm_fp16<1>,
                         cudaFuncAttributeMaxDynamicSharedMemorySize, GEMM_SMEM);
    cudaFuncSetAttribute(flash_attn_kernel,
                         cudaFuncAttributeMaxDynamicSharedMemorySize, FL_SMEM);

    // 0) fp16 conversions
    cvt_kernel<0><<<(Mm*Cc/4 + 255)/256, 256>>>(x,   Mm*Cc/4);
    cvt_kernel<1><<<(N1*Cc/4 + 255)/256, 256>>>(ipw, N1*Cc/4);
    cvt_kernel<2><<<(Cc*Cc/4 + 255)/256, 256>>>(opw, Cc*Cc/4);

    // 1) QKV projection + bias + fused RoPE -> Qh, Kh, Vt (fp16)
    {
        dim3 grid(N1 / 128, Mm / 128);
        gemm_fp16<0><<<grid, 256, GEMM_SMEM>>>(ipb, nullptr);
    }

    // 2) tensor-core causal flash attention (async K/V pipeline) -> g_yh
    {
        dim3 grid(Tt / 64, BHt);
        flash_attn_kernel<<<grid, 128, FL_SMEM>>>();
    }

    // 3) output projection + bias
    {
        dim3 grid(Cc / 128, Mm / 128);
        gemm_fp16<1><<<grid, 256, GEMM_SMEM>>>(opb, out);
    }
}